// round 2
// baseline (speedup 1.0000x reference)
#include <cuda_runtime.h>
#include <cuda_bf16.h>
#include <math.h>

// Problem constants
#define Bc   2
#define Lc   2048
#define DINc 512
#define DMc  1024
#define NSc  16
#define RKc  64
#define Mrows (Bc*Lc)   // 4096

// -------------------- scratch (static device memory; no allocs) -----------
__device__ float g_xpre [Mrows*DMc];
__device__ float g_res  [Mrows*DMc];
__device__ float g_xs   [Mrows*DMc];
__device__ float g_bp   [Mrows*NSc];
__device__ float g_cp   [Mrows*NSc];
__device__ float g_dtl  [Mrows*RKc];
__device__ float g_delta[Mrows*DMc];
__device__ float g_y    [Mrows*DMc];

__device__ __forceinline__ float siluf(float x) {
    return x / (1.0f + __expf(-x));
}

__device__ __forceinline__ unsigned long long dup_f32x2(float v) {
    unsigned long long r;
    asm("mov.b64 %0, {%1, %1};" : "=l"(r) : "r"(__float_as_uint(v)));
    return r;
}
__device__ __forceinline__ void fma_f32x2(unsigned long long& acc,
                                          unsigned long long a,
                                          unsigned long long b) {
    asm("fma.rn.f32x2 %0, %1, %2, %0;" : "+l"(acc) : "l"(a), "l"(b));
}
__device__ __forceinline__ float lo_f32(unsigned long long v) {
    return __uint_as_float((unsigned)(v & 0xffffffffull));
}
__device__ __forceinline__ float hi_f32(unsigned long long v) {
    return __uint_as_float((unsigned)(v >> 32));
}

// -------------------- generic C = A * B^T  (both K-major) -----------------
// A: [M, K] lda;  B: [N, K] ldb;  C: [M, N] ldc
// EPI: 0 = none, 1 = softplus(v + bias[n])
// For TN==8 uses packed fma.rn.f32x2 (FFMA2) with a split-j column mapping:
// thread tx owns columns [tx*4, tx*4+4) and [BN/2 + tx*4, BN/2 + tx*4+4).
template<int BM, int BN, int BK, int TM, int TN, int EPI>
__global__ __launch_bounds__((BM/TM)*(BN/TN))
void gemm_atb(const float* __restrict__ A, int lda,
              const float* __restrict__ Bmat, int ldb,
              const float* __restrict__ bias,
              float* __restrict__ C, int ldc, int K)
{
    constexpr bool V2 = (TN == 8) && (TM % 2 == 0);

    __shared__ float As[BK][BM + 8];   // +8 keeps rows 16B-aligned (544B stride)
    __shared__ float Bs[BK][BN + 8];

    const int tid = threadIdx.x;
    const int bm  = blockIdx.x * BM;
    const int bn  = blockIdx.y * BN;

    // float4 staging mapping: BK/4 float4 per row
    const int a_row = tid / (BK / 4);
    const int a_col = (tid % (BK / 4)) * 4;
    const bool b_act = (a_row < BN);

    const int ty = tid / (BN / TN);
    const int tx = tid % (BN / TN);

    const float* Aptr = A    + (size_t)(bm + a_row) * lda + a_col;
    const float* Bptr = Bmat + (size_t)(bn + (b_act ? a_row : 0)) * ldb + a_col;

    if constexpr (V2) {
        unsigned long long acc2[TM/2][TN] = {};   // (row 2i, row 2i+1) packed

        for (int k0 = 0; k0 < K; k0 += BK) {
            float4 av = *(const float4*)(Aptr + k0);
            As[a_col + 0][a_row] = av.x;
            As[a_col + 1][a_row] = av.y;
            As[a_col + 2][a_row] = av.z;
            As[a_col + 3][a_row] = av.w;
            if (b_act) {
                float4 bv = *(const float4*)(Bptr + k0);
                Bs[a_col + 0][a_row] = bv.x;
                Bs[a_col + 1][a_row] = bv.y;
                Bs[a_col + 2][a_row] = bv.z;
                Bs[a_col + 3][a_row] = bv.w;
            }
            __syncthreads();

            #pragma unroll
            for (int kk = 0; kk < BK; kk++) {
                // A row-pairs straight from shared as 64-bit loads
                unsigned long long a2[TM/2];
                #pragma unroll
                for (int i = 0; i < TM/2; i++)
                    a2[i] = *(const unsigned long long*)&As[kk][ty * TM + 2 * i];
                // B fragment: two conflict-free 128-bit loads (split halves)
                float4 b0 = *(const float4*)&Bs[kk][tx * 4];
                float4 b1 = *(const float4*)&Bs[kk][BN/2 + tx * 4];
                unsigned long long b2[TN];
                b2[0] = dup_f32x2(b0.x); b2[1] = dup_f32x2(b0.y);
                b2[2] = dup_f32x2(b0.z); b2[3] = dup_f32x2(b0.w);
                b2[4] = dup_f32x2(b1.x); b2[5] = dup_f32x2(b1.y);
                b2[6] = dup_f32x2(b1.z); b2[7] = dup_f32x2(b1.w);
                #pragma unroll
                for (int i = 0; i < TM/2; i++)
                    #pragma unroll
                    for (int j = 0; j < TN; j++)
                        fma_f32x2(acc2[i][j], a2[i], b2[j]);
            }
            __syncthreads();
        }

        // epilogue: two float4 chunks per row (cols tx*4 and BN/2+tx*4)
        #pragma unroll
        for (int i2 = 0; i2 < TM/2; i2++) {
            float vlo[TN], vhi[TN];
            #pragma unroll
            for (int j = 0; j < TN; j++) {
                vlo[j] = lo_f32(acc2[i2][j]);
                vhi[j] = hi_f32(acc2[i2][j]);
            }
            if (EPI == 1) {
                #pragma unroll
                for (int j = 0; j < TN; j++) {
                    int col = bn + ((j < 4) ? (tx * 4 + j) : (BN/2 + tx * 4 + j - 4));
                    float bb = bias[col];
                    float a1 = vlo[j] + bb;
                    float a2v = vhi[j] + bb;
                    vlo[j] = (a1  > 20.0f) ? a1  : log1pf(__expf(a1));
                    vhi[j] = (a2v > 20.0f) ? a2v : log1pf(__expf(a2v));
                }
            }
            const int r0 = bm + ty * TM + 2 * i2;
            float* c0 = C + (size_t)r0 * ldc + bn + tx * 4;
            float* c1 = C + (size_t)(r0 + 1) * ldc + bn + tx * 4;
            *(float4*)(c0)            = make_float4(vlo[0], vlo[1], vlo[2], vlo[3]);
            *(float4*)(c0 + BN/2)     = make_float4(vlo[4], vlo[5], vlo[6], vlo[7]);
            *(float4*)(c1)            = make_float4(vhi[0], vhi[1], vhi[2], vhi[3]);
            *(float4*)(c1 + BN/2)     = make_float4(vhi[4], vhi[5], vhi[6], vhi[7]);
        }
    } else {
        // ---------------- scalar fallback (skinny N) ----------------
        float acc[TM][TN] = {};

        for (int k0 = 0; k0 < K; k0 += BK) {
            float4 av = *(const float4*)(Aptr + k0);
            As[a_col + 0][a_row] = av.x;
            As[a_col + 1][a_row] = av.y;
            As[a_col + 2][a_row] = av.z;
            As[a_col + 3][a_row] = av.w;
            if (b_act) {
                float4 bv = *(const float4*)(Bptr + k0);
                Bs[a_col + 0][a_row] = bv.x;
                Bs[a_col + 1][a_row] = bv.y;
                Bs[a_col + 2][a_row] = bv.z;
                Bs[a_col + 3][a_row] = bv.w;
            }
            __syncthreads();

            #pragma unroll
            for (int kk = 0; kk < BK; kk++) {
                float af[TM], bf[TN];
                #pragma unroll
                for (int i = 0; i < TM; i++) af[i] = As[kk][ty * TM + i];
                #pragma unroll
                for (int j = 0; j < TN; j++) bf[j] = Bs[kk][tx * TN + j];
                #pragma unroll
                for (int i = 0; i < TM; i++)
                    #pragma unroll
                    for (int j = 0; j < TN; j++)
                        acc[i][j] = fmaf(af[i], bf[j], acc[i][j]);
            }
            __syncthreads();
        }

        #pragma unroll
        for (int i = 0; i < TM; i++) {
            const int m = bm + ty * TM + i;
            float* crow = C + (size_t)m * ldc + bn + tx * TN;
            #pragma unroll
            for (int j = 0; j < TN; j++) {
                float v1 = acc[i][j];
                if (EPI == 1) {
                    v1 += bias[bn + tx * TN + j];
                    v1 = (v1 > 20.0f) ? v1 : log1pf(__expf(v1));
                }
                crow[j] = v1;
            }
        }
    }
}

// -------------------- causal depthwise conv1d (K=4) + bias + silu ---------
__global__ __launch_bounds__(256)
void conv_silu_kernel(const float* __restrict__ xpre,
                      const float* __restrict__ w,      // (D, 1, 4) -> w[d*4+k]
                      const float* __restrict__ bias,
                      float* __restrict__ out)
{
    int idx = blockIdx.x * 256 + threadIdx.x;           // over B*L*D
    int d = idx & (DMc - 1);
    int l = (idx >> 10) & (Lc - 1);

    float4 wv = *(const float4*)(w + d * 4);            // 16B aligned
    float acc = bias[d];
    // out[l] = sum_k w[k] * x[l-3+k]
    if (l >= 3) acc = fmaf(wv.x, xpre[idx - 3 * DMc], acc);
    if (l >= 2) acc = fmaf(wv.y, xpre[idx - 2 * DMc], acc);
    if (l >= 1) acc = fmaf(wv.z, xpre[idx - 1 * DMc], acc);
    acc = fmaf(wv.w, xpre[idx], acc);
    out[idx] = siluf(acc);
}

// -------------------- selective scan --------------------------------------
// grid: (D/16, B), block: 256 threads.  thread = (dl = tid>>4, n = tid&15)
#define TS 128
__global__ __launch_bounds__(256)
void scan_kernel(const float* __restrict__ delta_g,
                 const float* __restrict__ xs_g,
                 const float* __restrict__ bp_g,
                 const float* __restrict__ cp_g,
                 const float* __restrict__ res_g,
                 const float* __restrict__ A_log,
                 const float* __restrict__ D_param,
                 float* __restrict__ y_g)
{
    __shared__ float sD[TS][16];
    __shared__ float sX[TS][16];
    __shared__ float sB[TS][16];
    __shared__ float sC[TS][16];
    __shared__ float sR[TS][16];
    __shared__ float sY[TS][16];

    const int b  = blockIdx.y;
    const int d0 = blockIdx.x * 16;
    const int tid = threadIdx.x;
    const int n  = tid & 15;
    const int dl = tid >> 4;
    const int d  = d0 + dl;

    const float a = -__expf(A_log[d * NSc + n]);   // A[d][n]  (negative)
    float h = 0.0f;

    const size_t rowbase = (size_t)b * Lc;

    for (int l0 = 0; l0 < Lc; l0 += TS) {
        // cooperative stage: TS*16 = 2048 elements, 256 threads -> 8 each
        #pragma unroll
        for (int i = tid; i < TS * 16; i += 256) {
            int r = i >> 4, c = i & 15;
            size_t g = (rowbase + l0 + r) * DMc + d0 + c;
            sD[r][c] = delta_g[g];
            sX[r][c] = xs_g[g];
            sR[r][c] = res_g[g];
        }
        #pragma unroll
        for (int i = tid; i < TS * 16; i += 256) {
            size_t g = (rowbase + l0) * NSc + i;
            sB[i >> 4][i & 15] = bp_g[g];
            sC[i >> 4][i & 15] = cp_g[g];
        }
        __syncthreads();

        #pragma unroll 4
        for (int t = 0; t < TS; t++) {
            float dt = sD[t][dl];
            float xv = sX[t][dl];
            float dA = __expf(dt * a);
            h = fmaf(dA, h, dt * xv * sB[t][n]);
            float contrib = h * sC[t][n];
            // reduce over the 16 states (stays inside 16-lane halves)
            contrib += __shfl_xor_sync(0xffffffffu, contrib, 8);
            contrib += __shfl_xor_sync(0xffffffffu, contrib, 4);
            contrib += __shfl_xor_sync(0xffffffffu, contrib, 2);
            contrib += __shfl_xor_sync(0xffffffffu, contrib, 1);
            if (n == 0) sY[t][dl] = contrib;
        }
        __syncthreads();

        // epilogue: y = (scan + xs*D) * silu(res), coalesced store
        #pragma unroll
        for (int i = tid; i < TS * 16; i += 256) {
            int r = i >> 4, c = i & 15;
            size_t g = (rowbase + l0 + r) * DMc + d0 + c;
            float rv = sR[r][c];
            y_g[g] = (sY[r][c] + sX[r][c] * D_param[d0 + c]) * siluf(rv);
        }
        __syncthreads();
    }
}

// -------------------- launch ----------------------------------------------
extern "C" void kernel_launch(void* const* d_in, const int* in_sizes, int n_in,
                              void* d_out, int out_size)
{
    const float* x_in     = (const float*)d_in[0];
    const float* W_in     = (const float*)d_in[1];
    const float* W_res    = (const float*)d_in[2];
    const float* W_out    = (const float*)d_in[3];
    const float* conv_w   = (const float*)d_in[4];
    const float* conv_b   = (const float*)d_in[5];
    const float* A_log    = (const float*)d_in[6];
    const float* D_param  = (const float*)d_in[7];
    const float* W_B      = (const float*)d_in[8];
    const float* W_C      = (const float*)d_in[9];
    const float* W_dt     = (const float*)d_in[10];
    const float* W_dtproj = (const float*)d_in[11];
    const float* b_dtproj = (const float*)d_in[12];
    float* out = (float*)d_out;

    float *xpre, *res, *xs, *bp, *cp, *dtl, *delta, *y;
    cudaGetSymbolAddress((void**)&xpre,  g_xpre);
    cudaGetSymbolAddress((void**)&res,   g_res);
    cudaGetSymbolAddress((void**)&xs,    g_xs);
    cudaGetSymbolAddress((void**)&bp,    g_bp);
    cudaGetSymbolAddress((void**)&cp,    g_cp);
    cudaGetSymbolAddress((void**)&dtl,   g_dtl);
    cudaGetSymbolAddress((void**)&delta, g_delta);
    cudaGetSymbolAddress((void**)&y,     g_y);

    // 1) x_pre = x_in @ W_in^T   (4096 x 1024, K=512)
    gemm_atb<128,128,8,8,8,0><<<dim3(Mrows/128, DMc/128), 256>>>(
        x_in, DINc, W_in, DINc, nullptr, xpre, DMc, DINc);
    // 2) res = x_in @ W_res^T
    gemm_atb<128,128,8,8,8,0><<<dim3(Mrows/128, DMc/128), 256>>>(
        x_in, DINc, W_res, DINc, nullptr, res, DMc, DINc);
    // 3) xs = silu(causal_conv(x_pre) + b)
    conv_silu_kernel<<<(Mrows * DMc) / 256, 256>>>(xpre, conv_w, conv_b, xs);
    // 4) Bp = xs @ W_B^T   (N=16)
    gemm_atb<128,16,8,8,1,0><<<dim3(Mrows/128, 1), 256>>>(
        xs, DMc, W_B, DMc, nullptr, bp, NSc, DMc);
    // 5) Cp = xs @ W_C^T
    gemm_atb<128,16,8,8,1,0><<<dim3(Mrows/128, 1), 256>>>(
        xs, DMc, W_C, DMc, nullptr, cp, NSc, DMc);
    // 6) dt_low = xs @ W_dt^T  (N=64)
    gemm_atb<128,64,8,8,4,0><<<dim3(Mrows/128, 1), 256>>>(
        xs, DMc, W_dt, DMc, nullptr, dtl, RKc, DMc);
    // 7) delta = softplus(dt_low @ W_dtproj^T + b_dtproj)
    gemm_atb<128,128,8,8,8,1><<<dim3(Mrows/128, DMc/128), 256>>>(
        dtl, RKc, W_dtproj, RKc, b_dtproj, delta, DMc, RKc);
    // 8) selective scan -> y (includes +xs*D and *silu(res))
    scan_kernel<<<dim3(DMc/16, Bc), 256>>>(delta, xs, bp, cp, res,
                                           A_log, D_param, y);
    // 9) out = y @ W_out^T  (4096 x 512, K=1024)
    gemm_atb<128,128,8,8,8,0><<<dim3(Mrows/128, DINc/128), 256>>>(
        y, DMc, W_out, DMc, nullptr, out, DINc, DMc);
}

// round 9
// speedup vs baseline: 1.3907x; 1.3907x over previous
#include <cuda_runtime.h>
#include <cuda_bf16.h>
#include <math.h>

// Problem constants
#define Bc   2
#define Lc   2048
#define DINc 512
#define DMc  1024
#define NSc  16
#define RKc  64
#define Mrows (Bc*Lc)   // 4096

// -------------------- scratch (static device memory; no allocs) -----------
__device__ float g_xpre [Mrows*DMc];
__device__ float g_res  [Mrows*DMc];
__device__ float g_xs   [Mrows*DMc];
__device__ float g_bp   [Mrows*NSc];
__device__ float g_cp   [Mrows*NSc];
__device__ float g_dtl  [Mrows*RKc];
__device__ float g_delta[Mrows*DMc];
__device__ float g_y    [Mrows*DMc];

__device__ __forceinline__ float siluf(float x) {
    return x / (1.0f + __expf(-x));
}

__device__ __forceinline__ unsigned long long dup_f32x2(float v) {
    unsigned long long r;
    asm("mov.b64 %0, {%1, %1};" : "=l"(r) : "r"(__float_as_uint(v)));
    return r;
}
__device__ __forceinline__ void fma_f32x2(unsigned long long& acc,
                                          unsigned long long a,
                                          unsigned long long b) {
    asm("fma.rn.f32x2 %0, %1, %2, %0;" : "+l"(acc) : "l"(a), "l"(b));
}
__device__ __forceinline__ float lo_f32(unsigned long long v) {
    return __uint_as_float((unsigned)(v & 0xffffffffull));
}
__device__ __forceinline__ float hi_f32(unsigned long long v) {
    return __uint_as_float((unsigned)(v >> 32));
}

// -------------------- 128x128 GEMM, C = A * B^T, FFMA2, double-buffered ---
// A: [M, K] lda;  B: [N, K] ldb;  C: [M, N] ldc.  K % 16 == 0.
// gridDim.z selects (B1,C1) or (B2,C2) — used to fuse x_pre & res launches.
// EPI: 0 = none, 1 = softplus(v + bias[n]).
// Thread tile 8x8 as 4 packed row-pairs; tx owns cols tx*4 and 64+tx*4.
#define GBM 128
#define GBN 128
#define GBK 16
template<int EPI>
__global__ __launch_bounds__(256)
void gemm128(const float* __restrict__ A, int lda,
             const float* __restrict__ B1, const float* __restrict__ B2, int ldb,
             const float* __restrict__ bias,
             float* __restrict__ C1, float* __restrict__ C2, int ldc, int K)
{
    __shared__ float As[2][GBK][GBM + 8];
    __shared__ float Bs[2][GBK][GBN + 8];

    const float* Bmat = (blockIdx.z == 0) ? B1 : B2;
    float*       C    = (blockIdx.z == 0) ? C1 : C2;

    const int tid = threadIdx.x;
    const int bm  = blockIdx.x * GBM;
    const int bn  = blockIdx.y * GBN;

    // staging: each thread loads 2 float4 from A and 2 from B per k-step
    const int s_row = tid >> 2;          // 0..63  (and +64)
    const int s_col = (tid & 3) * 4;     // 0,4,8,12

    const int ty = tid >> 4;             // 0..15 -> rows ty*8 .. ty*8+7
    const int tx = tid & 15;             // 0..15 -> cols tx*4 and 64+tx*4

    const float* Aptr = A    + (size_t)(bm + s_row) * lda + s_col;
    const float* Bptr = Bmat + (size_t)(bn + s_row) * ldb + s_col;

    unsigned long long acc2[4][8] = {};  // (row 2i, row 2i+1) packed

    const int niter = K / GBK;

    // prologue: stage k0 = 0 into buffer 0
    {
        float4 a0 = *(const float4*)(Aptr);
        float4 a1 = *(const float4*)(Aptr + (size_t)64 * lda);
        float4 b0 = *(const float4*)(Bptr);
        float4 b1 = *(const float4*)(Bptr + (size_t)64 * ldb);
        As[0][s_col+0][s_row] = a0.x; As[0][s_col+1][s_row] = a0.y;
        As[0][s_col+2][s_row] = a0.z; As[0][s_col+3][s_row] = a0.w;
        As[0][s_col+0][s_row+64] = a1.x; As[0][s_col+1][s_row+64] = a1.y;
        As[0][s_col+2][s_row+64] = a1.z; As[0][s_col+3][s_row+64] = a1.w;
        Bs[0][s_col+0][s_row] = b0.x; Bs[0][s_col+1][s_row] = b0.y;
        Bs[0][s_col+2][s_row] = b0.z; Bs[0][s_col+3][s_row] = b0.w;
        Bs[0][s_col+0][s_row+64] = b1.x; Bs[0][s_col+1][s_row+64] = b1.y;
        Bs[0][s_col+2][s_row+64] = b1.z; Bs[0][s_col+3][s_row+64] = b1.w;
    }
    __syncthreads();

    for (int i = 0; i < niter; i++) {
        const int cur = i & 1;
        float4 a0, a1, b0, b1;
        const bool more = (i + 1 < niter);
        if (more) {
            const int k0 = (i + 1) * GBK;
            a0 = *(const float4*)(Aptr + k0);
            a1 = *(const float4*)(Aptr + k0 + (size_t)64 * lda);
            b0 = *(const float4*)(Bptr + k0);
            b1 = *(const float4*)(Bptr + k0 + (size_t)64 * ldb);
        }

        #pragma unroll
        for (int kk = 0; kk < GBK; kk++) {
            unsigned long long a2[4];
            #pragma unroll
            for (int u = 0; u < 4; u++)
                a2[u] = *(const unsigned long long*)&As[cur][kk][ty * 8 + 2 * u];
            float4 f0 = *(const float4*)&Bs[cur][kk][tx * 4];
            float4 f1 = *(const float4*)&Bs[cur][kk][64 + tx * 4];
            unsigned long long b2[8];
            b2[0] = dup_f32x2(f0.x); b2[1] = dup_f32x2(f0.y);
            b2[2] = dup_f32x2(f0.z); b2[3] = dup_f32x2(f0.w);
            b2[4] = dup_f32x2(f1.x); b2[5] = dup_f32x2(f1.y);
            b2[6] = dup_f32x2(f1.z); b2[7] = dup_f32x2(f1.w);
            #pragma unroll
            for (int u = 0; u < 4; u++)
                #pragma unroll
                for (int j = 0; j < 8; j++)
                    fma_f32x2(acc2[u][j], a2[u], b2[j]);
        }

        if (more) {
            const int nxt = cur ^ 1;
            As[nxt][s_col+0][s_row] = a0.x; As[nxt][s_col+1][s_row] = a0.y;
            As[nxt][s_col+2][s_row] = a0.z; As[nxt][s_col+3][s_row] = a0.w;
            As[nxt][s_col+0][s_row+64] = a1.x; As[nxt][s_col+1][s_row+64] = a1.y;
            As[nxt][s_col+2][s_row+64] = a1.z; As[nxt][s_col+3][s_row+64] = a1.w;
            Bs[nxt][s_col+0][s_row] = b0.x; Bs[nxt][s_col+1][s_row] = b0.y;
            Bs[nxt][s_col+2][s_row] = b0.z; Bs[nxt][s_col+3][s_row] = b0.w;
            Bs[nxt][s_col+0][s_row+64] = b1.x; Bs[nxt][s_col+1][s_row+64] = b1.y;
            Bs[nxt][s_col+2][s_row+64] = b1.z; Bs[nxt][s_col+3][s_row+64] = b1.w;
        }
        __syncthreads();
    }

    // epilogue: two float4 chunks per row (cols tx*4 and 64+tx*4)
    #pragma unroll
    for (int i2 = 0; i2 < 4; i2++) {
        float vlo[8], vhi[8];
        #pragma unroll
        for (int j = 0; j < 8; j++) {
            vlo[j] = lo_f32(acc2[i2][j]);
            vhi[j] = hi_f32(acc2[i2][j]);
        }
        if (EPI == 1) {
            #pragma unroll
            for (int j = 0; j < 8; j++) {
                int col = bn + ((j < 4) ? (tx * 4 + j) : (64 + tx * 4 + j - 4));
                float bb = bias[col];
                float a1v = vlo[j] + bb;
                float a2v = vhi[j] + bb;
                vlo[j] = (a1v > 20.0f) ? a1v : log1pf(__expf(a1v));
                vhi[j] = (a2v > 20.0f) ? a2v : log1pf(__expf(a2v));
            }
        }
        const int r0 = bm + ty * 8 + 2 * i2;
        float* c0 = C + (size_t)r0 * ldc + bn + tx * 4;
        float* c1 = C + (size_t)(r0 + 1) * ldc + bn + tx * 4;
        *(float4*)(c0)      = make_float4(vlo[0], vlo[1], vlo[2], vlo[3]);
        *(float4*)(c0 + 64) = make_float4(vlo[4], vlo[5], vlo[6], vlo[7]);
        *(float4*)(c1)      = make_float4(vhi[0], vhi[1], vhi[2], vhi[3]);
        *(float4*)(c1 + 64) = make_float4(vhi[4], vhi[5], vhi[6], vhi[7]);
    }
}

// -------------------- fused skinny projections: [Bp | Cp | dt_low] --------
// C_all[4096, 96] = xs[4096, 1024] @ [W_B; W_C; W_dt]^T
// BM=32, BK=32, 256 threads, 2x6 register tile, grid = 128 blocks.
#define PBM 32
#define PBK 32
#define PN  96
__global__ __launch_bounds__(256)
void proj_bcdt(const float* __restrict__ xs,
               const float* __restrict__ W_B,
               const float* __restrict__ W_C,
               const float* __restrict__ W_dt,
               float* __restrict__ bp,
               float* __restrict__ cp,
               float* __restrict__ dtl)
{
    __shared__ float As[PBK][PBM + 4];
    __shared__ float Bs[PBK][PN + 4];

    const int tid = threadIdx.x;
    const int bm  = blockIdx.x * PBM;

    // A staging: 32 rows x 32 k = 256 float4; one per thread
    const int a_row = tid >> 3;
    const int a_col = (tid & 7) * 4;
    const float* Aptr = xs + (size_t)(bm + a_row) * DMc + a_col;

    // B staging: 96 weight rows x 8 float4 = 768 float4; 3 per thread
    const float* wrow[3];
    int wk[3], wr[3];
    #pragma unroll
    for (int i = 0; i < 3; i++) {
        int f = tid + 256 * i;
        int r = f >> 3;
        wr[i] = r;
        wk[i] = (f & 7) * 4;
        wrow[i] = (r < 16) ? (W_B + (size_t)r * DMc)
                : (r < 32) ? (W_C + (size_t)(r - 16) * DMc)
                           : (W_dt + (size_t)(r - 32) * DMc);
    }

    const int ty = tid >> 4;    // 0..15 -> rows ty*2 + {0,1}
    const int tx = tid & 15;    // 0..15 -> cols tx*6 + {0..5}
    float acc[2][6] = {};

    for (int k0 = 0; k0 < DMc; k0 += PBK) {
        float4 av = *(const float4*)(Aptr + k0);
        As[a_col + 0][a_row] = av.x;
        As[a_col + 1][a_row] = av.y;
        As[a_col + 2][a_row] = av.z;
        As[a_col + 3][a_row] = av.w;
        #pragma unroll
        for (int i = 0; i < 3; i++) {
            float4 bv = *(const float4*)(wrow[i] + k0 + wk[i]);
            Bs[wk[i] + 0][wr[i]] = bv.x;
            Bs[wk[i] + 1][wr[i]] = bv.y;
            Bs[wk[i] + 2][wr[i]] = bv.z;
            Bs[wk[i] + 3][wr[i]] = bv.w;
        }
        __syncthreads();

        #pragma unroll
        for (int kk = 0; kk < PBK; kk++) {
            float a0 = As[kk][ty * 2 + 0];
            float a1 = As[kk][ty * 2 + 1];
            #pragma unroll
            for (int j = 0; j < 6; j++) {
                float b = Bs[kk][tx * 6 + j];
                acc[0][j] = fmaf(a0, b, acc[0][j]);
                acc[1][j] = fmaf(a1, b, acc[1][j]);
            }
        }
        __syncthreads();
    }

    // scatter stores into the three destination buffers
    #pragma unroll
    for (int i = 0; i < 2; i++) {
        const int row = bm + ty * 2 + i;
        #pragma unroll
        for (int j = 0; j < 6; j++) {
            const int c = tx * 6 + j;
            const float v = acc[i][j];
            if (c < 16)      bp [(size_t)row * NSc + c]        = v;
            else if (c < 32) cp [(size_t)row * NSc + (c - 16)] = v;
            else             dtl[(size_t)row * RKc + (c - 32)] = v;
        }
    }
}

// -------- causal depthwise conv1d (K=4) + bias + silu, float4 over d ------
__global__ __launch_bounds__(256)
void conv_silu_kernel(const float* __restrict__ xpre,
                      const float* __restrict__ w,      // (D, 1, 4) -> w[d*4+k]
                      const float* __restrict__ bias,
                      float* __restrict__ out)
{
    const int t = blockIdx.x * 256 + threadIdx.x;       // over B*L*D/4
    const int e = t * 4;                                // first element index
    const int d = e & (DMc - 1);                        // multiple of 4
    const int l = (e >> 10) & (Lc - 1);                 // DMc = 1024 = 2^10

    float4 x0  = *(const float4*)(xpre + e);
    float4 xm1 = (l >= 1) ? *(const float4*)(xpre + e - 1 * DMc) : make_float4(0,0,0,0);
    float4 xm2 = (l >= 2) ? *(const float4*)(xpre + e - 2 * DMc) : make_float4(0,0,0,0);
    float4 xm3 = (l >= 3) ? *(const float4*)(xpre + e - 3 * DMc) : make_float4(0,0,0,0);
    float4 bb  = *(const float4*)(bias + d);

    float4 r;
    {
        float4 wv = *(const float4*)(w + (d + 0) * 4);
        r.x = fmaf(wv.x, xm3.x, fmaf(wv.y, xm2.x, fmaf(wv.z, xm1.x, fmaf(wv.w, x0.x, bb.x))));
    }
    {
        float4 wv = *(const float4*)(w + (d + 1) * 4);
        r.y = fmaf(wv.x, xm3.y, fmaf(wv.y, xm2.y, fmaf(wv.z, xm1.y, fmaf(wv.w, x0.y, bb.y))));
    }
    {
        float4 wv = *(const float4*)(w + (d + 2) * 4);
        r.z = fmaf(wv.x, xm3.z, fmaf(wv.y, xm2.z, fmaf(wv.z, xm1.z, fmaf(wv.w, x0.z, bb.z))));
    }
    {
        float4 wv = *(const float4*)(w + (d + 3) * 4);
        r.w = fmaf(wv.x, xm3.w, fmaf(wv.y, xm2.w, fmaf(wv.z, xm1.w, fmaf(wv.w, x0.w, bb.w))));
    }
    r.x = siluf(r.x); r.y = siluf(r.y); r.z = siluf(r.z); r.w = siluf(r.w);
    *(float4*)(out + e) = r;
}

// -------------------- selective scan --------------------------------------
// grid: (D/16, B), block: 256 threads.  thread = (dl = tid>>4, n = tid&15)
#define TS 128
__global__ __launch_bounds__(256)
void scan_kernel(const float* __restrict__ delta_g,
                 const float* __restrict__ xs_g,
                 const float* __restrict__ bp_g,
                 const float* __restrict__ cp_g,
                 const float* __restrict__ res_g,
                 const float* __restrict__ A_log,
                 const float* __restrict__ D_param,
                 float* __restrict__ y_g)
{
    __shared__ float sD[TS][16];
    __shared__ float sX[TS][16];
    __shared__ float sB[TS][16];
    __shared__ float sC[TS][16];
    __shared__ float sR[TS][16];
    __shared__ float sY[TS][16];

    const int b  = blockIdx.y;
    const int d0 = blockIdx.x * 16;
    const int tid = threadIdx.x;
    const int n  = tid & 15;
    const int dl = tid >> 4;
    const int d  = d0 + dl;

    const float a = -__expf(A_log[d * NSc + n]);   // A[d][n]  (negative)
    float h = 0.0f;

    const size_t rowbase = (size_t)b * Lc;

    for (int l0 = 0; l0 < Lc; l0 += TS) {
        // cooperative stage: TS*16 = 2048 elements, 256 threads -> 8 each
        #pragma unroll
        for (int i = tid; i < TS * 16; i += 256) {
            int r = i >> 4, c = i & 15;
            size_t g = (rowbase + l0 + r) * DMc + d0 + c;
            sD[r][c] = delta_g[g];
            sX[r][c] = xs_g[g];
            sR[r][c] = res_g[g];
        }
        #pragma unroll
        for (int i = tid; i < TS * 16; i += 256) {
            size_t g = (rowbase + l0) * NSc + i;
            sB[i >> 4][i & 15] = bp_g[g];
            sC[i >> 4][i & 15] = cp_g[g];
        }
        __syncthreads();

        #pragma unroll 4
        for (int t = 0; t < TS; t++) {
            float dt = sD[t][dl];
            float xv = sX[t][dl];
            float dA = __expf(dt * a);
            h = fmaf(dA, h, dt * xv * sB[t][n]);
            float contrib = h * sC[t][n];
            // reduce over the 16 states (stays inside 16-lane halves)
            contrib += __shfl_xor_sync(0xffffffffu, contrib, 8);
            contrib += __shfl_xor_sync(0xffffffffu, contrib, 4);
            contrib += __shfl_xor_sync(0xffffffffu, contrib, 2);
            contrib += __shfl_xor_sync(0xffffffffu, contrib, 1);
            if (n == 0) sY[t][dl] = contrib;
        }
        __syncthreads();

        // epilogue: y = (scan + xs*D) * silu(res), coalesced store
        #pragma unroll
        for (int i = tid; i < TS * 16; i += 256) {
            int r = i >> 4, c = i & 15;
            size_t g = (rowbase + l0 + r) * DMc + d0 + c;
            float rv = sR[r][c];
            y_g[g] = (sY[r][c] + sX[r][c] * D_param[d0 + c]) * siluf(rv);
        }
        __syncthreads();
    }
}

// -------------------- launch ----------------------------------------------
extern "C" void kernel_launch(void* const* d_in, const int* in_sizes, int n_in,
                              void* d_out, int out_size)
{
    const float* x_in     = (const float*)d_in[0];
    const float* W_in     = (const float*)d_in[1];
    const float* W_res    = (const float*)d_in[2];
    const float* W_out    = (const float*)d_in[3];
    const float* conv_w   = (const float*)d_in[4];
    const float* conv_b   = (const float*)d_in[5];
    const float* A_log    = (const float*)d_in[6];
    const float* D_param  = (const float*)d_in[7];
    const float* W_B      = (const float*)d_in[8];
    const float* W_C      = (const float*)d_in[9];
    const float* W_dt     = (const float*)d_in[10];
    const float* W_dtproj = (const float*)d_in[11];
    const float* b_dtproj = (const float*)d_in[12];
    float* out = (float*)d_out;

    float *xpre, *res, *xs, *bp, *cp, *dtl, *delta, *y;
    cudaGetSymbolAddress((void**)&xpre,  g_xpre);
    cudaGetSymbolAddress((void**)&res,   g_res);
    cudaGetSymbolAddress((void**)&xs,    g_xs);
    cudaGetSymbolAddress((void**)&bp,    g_bp);
    cudaGetSymbolAddress((void**)&cp,    g_cp);
    cudaGetSymbolAddress((void**)&dtl,   g_dtl);
    cudaGetSymbolAddress((void**)&delta, g_delta);
    cudaGetSymbolAddress((void**)&y,     g_y);

    // 1+2) x_pre = x_in @ W_in^T ; res = x_in @ W_res^T  (fused, grid.z=2)
    gemm128<0><<<dim3(Mrows/GBM, DMc/GBN, 2), 256>>>(
        x_in, DINc, W_in, W_res, DINc, nullptr, xpre, res, DMc, DINc);
    // 3) xs = silu(causal_conv(x_pre) + b)   (float4 over d)
    conv_silu_kernel<<<(Mrows * DMc / 4) / 256, 256>>>(xpre, conv_w, conv_b, xs);
    // 4-6) fused skinny projections: Bp, Cp, dt_low in one pass over xs
    proj_bcdt<<<Mrows / PBM, 256>>>(xs, W_B, W_C, W_dt, bp, cp, dtl);
    // 7) delta = softplus(dt_low @ W_dtproj^T + b_dtproj)
    gemm128<1><<<dim3(Mrows/GBM, DMc/GBN, 1), 256>>>(
        dtl, RKc, W_dtproj, W_dtproj, RKc, b_dtproj, delta, delta, DMc, RKc);
    // 8) selective scan -> y (includes +xs*D and *silu(res))
    scan_kernel<<<dim3(DMc/16, Bc), 256>>>(delta, xs, bp, cp, res,
                                           A_log, D_param, y);
    // 9) out = y @ W_out^T  (4096 x 512, K=1024)
    gemm128<0><<<dim3(Mrows/GBM, DINc/GBN, 1), 256>>>(
        y, DMc, W_out, W_out, DMc, nullptr, out, out, DINc, DMc);
}

// round 13
// speedup vs baseline: 1.4600x; 1.0498x over previous
#include <cuda_runtime.h>
#include <cuda_bf16.h>
#include <math.h>

// Problem constants
#define Bc   2
#define Lc   2048
#define DINc 512
#define DMc  1024
#define NSc  16
#define RKc  64
#define Mrows (Bc*Lc)   // 4096

// -------------------- scratch (static device memory; no allocs) -----------
__device__ float g_xpre [Mrows*DMc];
__device__ float g_res  [Mrows*DMc];
__device__ float g_xs   [Mrows*DMc];
__device__ float g_bp   [Mrows*NSc];
__device__ float g_cp   [Mrows*NSc];
__device__ float g_dtl  [Mrows*RKc];
__device__ float g_delta[Mrows*DMc];
__device__ float g_y    [Mrows*DMc];

__device__ __forceinline__ float siluf(float x) {
    return x / (1.0f + __expf(-x));
}

__device__ __forceinline__ unsigned long long dup_f32x2(float v) {
    unsigned long long r;
    asm("mov.b64 %0, {%1, %1};" : "=l"(r) : "r"(__float_as_uint(v)));
    return r;
}
__device__ __forceinline__ void fma_f32x2(unsigned long long& acc,
                                          unsigned long long a,
                                          unsigned long long b) {
    asm("fma.rn.f32x2 %0, %1, %2, %0;" : "+l"(acc) : "l"(a), "l"(b));
}
__device__ __forceinline__ float lo_f32(unsigned long long v) {
    return __uint_as_float((unsigned)(v & 0xffffffffull));
}
__device__ __forceinline__ float hi_f32(unsigned long long v) {
    return __uint_as_float((unsigned)(v >> 32));
}

// -------------------- 128x128 GEMM, C = A * B^T, FFMA2, double-buffered ---
// A: [M, K] lda;  B: [N, K] ldb;  C: [M, N] ldc.  K % 16 == 0.
// gridDim.z selects (B1,C1) or (B2,C2) — used to fuse x_pre & res launches.
// EPI: 0 = none, 1 = softplus(v + bias[n]).
// Thread tile 8x8 as 4 packed row-pairs; tx owns cols tx*4 and 64+tx*4.
// __launch_bounds__(256, 2): cap regs at 128 so 2 CTAs/SM co-reside
// (R9 profile: regs=138 -> 1 CTA/SM, occ 12.3%, issue 41.5% = latency-bound).
#define GBM 128
#define GBN 128
#define GBK 16
template<int EPI>
__global__ __launch_bounds__(256, 2)
void gemm128(const float* __restrict__ A, int lda,
             const float* __restrict__ B1, const float* __restrict__ B2, int ldb,
             const float* __restrict__ bias,
             float* __restrict__ C1, float* __restrict__ C2, int ldc, int K)
{
    __shared__ float As[2][GBK][GBM + 8];
    __shared__ float Bs[2][GBK][GBN + 8];

    const float* Bmat = (blockIdx.z == 0) ? B1 : B2;
    float*       C    = (blockIdx.z == 0) ? C1 : C2;

    const int tid = threadIdx.x;
    const int bm  = blockIdx.x * GBM;
    const int bn  = blockIdx.y * GBN;

    // staging: each thread loads 2 float4 from A and 2 from B per k-step
    const int s_row = tid >> 2;          // 0..63  (and +64)
    const int s_col = (tid & 3) * 4;     // 0,4,8,12

    const int ty = tid >> 4;             // 0..15 -> rows ty*8 .. ty*8+7
    const int tx = tid & 15;             // 0..15 -> cols tx*4 and 64+tx*4

    const float* Aptr = A    + (size_t)(bm + s_row) * lda + s_col;
    const float* Bptr = Bmat + (size_t)(bn + s_row) * ldb + s_col;

    unsigned long long acc2[4][8] = {};  // (row 2i, row 2i+1) packed

    const int niter = K / GBK;

    // prologue: stage k0 = 0 into buffer 0
    {
        float4 a0 = *(const float4*)(Aptr);
        float4 a1 = *(const float4*)(Aptr + (size_t)64 * lda);
        float4 b0 = *(const float4*)(Bptr);
        float4 b1 = *(const float4*)(Bptr + (size_t)64 * ldb);
        As[0][s_col+0][s_row] = a0.x; As[0][s_col+1][s_row] = a0.y;
        As[0][s_col+2][s_row] = a0.z; As[0][s_col+3][s_row] = a0.w;
        As[0][s_col+0][s_row+64] = a1.x; As[0][s_col+1][s_row+64] = a1.y;
        As[0][s_col+2][s_row+64] = a1.z; As[0][s_col+3][s_row+64] = a1.w;
        Bs[0][s_col+0][s_row] = b0.x; Bs[0][s_col+1][s_row] = b0.y;
        Bs[0][s_col+2][s_row] = b0.z; Bs[0][s_col+3][s_row] = b0.w;
        Bs[0][s_col+0][s_row+64] = b1.x; Bs[0][s_col+1][s_row+64] = b1.y;
        Bs[0][s_col+2][s_row+64] = b1.z; Bs[0][s_col+3][s_row+64] = b1.w;
    }
    __syncthreads();

    for (int i = 0; i < niter; i++) {
        const int cur = i & 1;
        float4 a0, a1, b0, b1;
        const bool more = (i + 1 < niter);
        if (more) {
            const int k0 = (i + 1) * GBK;
            a0 = *(const float4*)(Aptr + k0);
            a1 = *(const float4*)(Aptr + k0 + (size_t)64 * lda);
            b0 = *(const float4*)(Bptr + k0);
            b1 = *(const float4*)(Bptr + k0 + (size_t)64 * ldb);
        }

        #pragma unroll
        for (int kk = 0; kk < GBK; kk++) {
            unsigned long long a2[4];
            #pragma unroll
            for (int u = 0; u < 4; u++)
                a2[u] = *(const unsigned long long*)&As[cur][kk][ty * 8 + 2 * u];
            float4 f0 = *(const float4*)&Bs[cur][kk][tx * 4];
            float4 f1 = *(const float4*)&Bs[cur][kk][64 + tx * 4];
            unsigned long long b2[8];
            b2[0] = dup_f32x2(f0.x); b2[1] = dup_f32x2(f0.y);
            b2[2] = dup_f32x2(f0.z); b2[3] = dup_f32x2(f0.w);
            b2[4] = dup_f32x2(f1.x); b2[5] = dup_f32x2(f1.y);
            b2[6] = dup_f32x2(f1.z); b2[7] = dup_f32x2(f1.w);
            #pragma unroll
            for (int u = 0; u < 4; u++)
                #pragma unroll
                for (int j = 0; j < 8; j++)
                    fma_f32x2(acc2[u][j], a2[u], b2[j]);
        }

        if (more) {
            const int nxt = cur ^ 1;
            As[nxt][s_col+0][s_row] = a0.x; As[nxt][s_col+1][s_row] = a0.y;
            As[nxt][s_col+2][s_row] = a0.z; As[nxt][s_col+3][s_row] = a0.w;
            As[nxt][s_col+0][s_row+64] = a1.x; As[nxt][s_col+1][s_row+64] = a1.y;
            As[nxt][s_col+2][s_row+64] = a1.z; As[nxt][s_col+3][s_row+64] = a1.w;
            Bs[nxt][s_col+0][s_row] = b0.x; Bs[nxt][s_col+1][s_row] = b0.y;
            Bs[nxt][s_col+2][s_row] = b0.z; Bs[nxt][s_col+3][s_row] = b0.w;
            Bs[nxt][s_col+0][s_row+64] = b1.x; Bs[nxt][s_col+1][s_row+64] = b1.y;
            Bs[nxt][s_col+2][s_row+64] = b1.z; Bs[nxt][s_col+3][s_row+64] = b1.w;
        }
        __syncthreads();
    }

    // epilogue: two float4 chunks per row (cols tx*4 and 64+tx*4)
    #pragma unroll
    for (int i2 = 0; i2 < 4; i2++) {
        float vlo[8], vhi[8];
        #pragma unroll
        for (int j = 0; j < 8; j++) {
            vlo[j] = lo_f32(acc2[i2][j]);
            vhi[j] = hi_f32(acc2[i2][j]);
        }
        if (EPI == 1) {
            #pragma unroll
            for (int j = 0; j < 8; j++) {
                int col = bn + ((j < 4) ? (tx * 4 + j) : (64 + tx * 4 + j - 4));
                float bb = bias[col];
                float a1v = vlo[j] + bb;
                float a2v = vhi[j] + bb;
                vlo[j] = (a1v > 20.0f) ? a1v : log1pf(__expf(a1v));
                vhi[j] = (a2v > 20.0f) ? a2v : log1pf(__expf(a2v));
            }
        }
        const int r0 = bm + ty * 8 + 2 * i2;
        float* c0 = C + (size_t)r0 * ldc + bn + tx * 4;
        float* c1 = C + (size_t)(r0 + 1) * ldc + bn + tx * 4;
        *(float4*)(c0)      = make_float4(vlo[0], vlo[1], vlo[2], vlo[3]);
        *(float4*)(c0 + 64) = make_float4(vlo[4], vlo[5], vlo[6], vlo[7]);
        *(float4*)(c1)      = make_float4(vhi[0], vhi[1], vhi[2], vhi[3]);
        *(float4*)(c1 + 64) = make_float4(vhi[4], vhi[5], vhi[6], vhi[7]);
    }
}

// -------------------- fused skinny projections: [Bp | Cp | dt_low] --------
// C_all[4096, 96] = xs[4096, 1024] @ [W_B; W_C; W_dt]^T
// BM=32, BK=32, 256 threads, 2x6 register tile, grid = 128 blocks.
#define PBM 32
#define PBK 32
#define PN  96
__global__ __launch_bounds__(256)
void proj_bcdt(const float* __restrict__ xs,
               const float* __restrict__ W_B,
               const float* __restrict__ W_C,
               const float* __restrict__ W_dt,
               float* __restrict__ bp,
               float* __restrict__ cp,
               float* __restrict__ dtl)
{
    __shared__ float As[PBK][PBM + 4];
    __shared__ float Bs[PBK][PN + 4];

    const int tid = threadIdx.x;
    const int bm  = blockIdx.x * PBM;

    // A staging: 32 rows x 32 k = 256 float4; one per thread
    const int a_row = tid >> 3;
    const int a_col = (tid & 7) * 4;
    const float* Aptr = xs + (size_t)(bm + a_row) * DMc + a_col;

    // B staging: 96 weight rows x 8 float4 = 768 float4; 3 per thread
    const float* wrow[3];
    int wk[3], wr[3];
    #pragma unroll
    for (int i = 0; i < 3; i++) {
        int f = tid + 256 * i;
        int r = f >> 3;
        wr[i] = r;
        wk[i] = (f & 7) * 4;
        wrow[i] = (r < 16) ? (W_B + (size_t)r * DMc)
                : (r < 32) ? (W_C + (size_t)(r - 16) * DMc)
                           : (W_dt + (size_t)(r - 32) * DMc);
    }

    const int ty = tid >> 4;    // 0..15 -> rows ty*2 + {0,1}
    const int tx = tid & 15;    // 0..15 -> cols tx*6 + {0..5}
    float acc[2][6] = {};

    for (int k0 = 0; k0 < DMc; k0 += PBK) {
        float4 av = *(const float4*)(Aptr + k0);
        As[a_col + 0][a_row] = av.x;
        As[a_col + 1][a_row] = av.y;
        As[a_col + 2][a_row] = av.z;
        As[a_col + 3][a_row] = av.w;
        #pragma unroll
        for (int i = 0; i < 3; i++) {
            float4 bv = *(const float4*)(wrow[i] + k0 + wk[i]);
            Bs[wk[i] + 0][wr[i]] = bv.x;
            Bs[wk[i] + 1][wr[i]] = bv.y;
            Bs[wk[i] + 2][wr[i]] = bv.z;
            Bs[wk[i] + 3][wr[i]] = bv.w;
        }
        __syncthreads();

        #pragma unroll
        for (int kk = 0; kk < PBK; kk++) {
            float a0 = As[kk][ty * 2 + 0];
            float a1 = As[kk][ty * 2 + 1];
            #pragma unroll
            for (int j = 0; j < 6; j++) {
                float b = Bs[kk][tx * 6 + j];
                acc[0][j] = fmaf(a0, b, acc[0][j]);
                acc[1][j] = fmaf(a1, b, acc[1][j]);
            }
        }
        __syncthreads();
    }

    // scatter stores into the three destination buffers
    #pragma unroll
    for (int i = 0; i < 2; i++) {
        const int row = bm + ty * 2 + i;
        #pragma unroll
        for (int j = 0; j < 6; j++) {
            const int c = tx * 6 + j;
            const float v = acc[i][j];
            if (c < 16)      bp [(size_t)row * NSc + c]        = v;
            else if (c < 32) cp [(size_t)row * NSc + (c - 16)] = v;
            else             dtl[(size_t)row * RKc + (c - 32)] = v;
        }
    }
}

// -------- causal depthwise conv1d (K=4) + bias + silu, float4 over d ------
__global__ __launch_bounds__(256)
void conv_silu_kernel(const float* __restrict__ xpre,
                      const float* __restrict__ w,      // (D, 1, 4) -> w[d*4+k]
                      const float* __restrict__ bias,
                      float* __restrict__ out)
{
    const int t = blockIdx.x * 256 + threadIdx.x;       // over B*L*D/4
    const int e = t * 4;                                // first element index
    const int d = e & (DMc - 1);                        // multiple of 4
    const int l = (e >> 10) & (Lc - 1);                 // DMc = 1024 = 2^10

    float4 x0  = *(const float4*)(xpre + e);
    float4 xm1 = (l >= 1) ? *(const float4*)(xpre + e - 1 * DMc) : make_float4(0,0,0,0);
    float4 xm2 = (l >= 2) ? *(const float4*)(xpre + e - 2 * DMc) : make_float4(0,0,0,0);
    float4 xm3 = (l >= 3) ? *(const float4*)(xpre + e - 3 * DMc) : make_float4(0,0,0,0);
    float4 bb  = *(const float4*)(bias + d);

    float4 r;
    {
        float4 wv = *(const float4*)(w + (d + 0) * 4);
        r.x = fmaf(wv.x, xm3.x, fmaf(wv.y, xm2.x, fmaf(wv.z, xm1.x, fmaf(wv.w, x0.x, bb.x))));
    }
    {
        float4 wv = *(const float4*)(w + (d + 1) * 4);
        r.y = fmaf(wv.x, xm3.y, fmaf(wv.y, xm2.y, fmaf(wv.z, xm1.y, fmaf(wv.w, x0.y, bb.y))));
    }
    {
        float4 wv = *(const float4*)(w + (d + 2) * 4);
        r.z = fmaf(wv.x, xm3.z, fmaf(wv.y, xm2.z, fmaf(wv.z, xm1.z, fmaf(wv.w, x0.z, bb.z))));
    }
    {
        float4 wv = *(const float4*)(w + (d + 3) * 4);
        r.w = fmaf(wv.x, xm3.w, fmaf(wv.y, xm2.w, fmaf(wv.z, xm1.w, fmaf(wv.w, x0.w, bb.w))));
    }
    r.x = siluf(r.x); r.y = siluf(r.y); r.z = siluf(r.z); r.w = siluf(r.w);
    *(float4*)(out + e) = r;
}

// -------------------- selective scan --------------------------------------
// grid: (D/16, B), block: 256 threads.  thread = (dl = tid>>4, n = tid&15)
#define TS 128
__global__ __launch_bounds__(256)
void scan_kernel(const float* __restrict__ delta_g,
                 const float* __restrict__ xs_g,
                 const float* __restrict__ bp_g,
                 const float* __restrict__ cp_g,
                 const float* __restrict__ res_g,
                 const float* __restrict__ A_log,
                 const float* __restrict__ D_param,
                 float* __restrict__ y_g)
{
    __shared__ float sD[TS][16];
    __shared__ float sX[TS][16];
    __shared__ float sB[TS][16];
    __shared__ float sC[TS][16];
    __shared__ float sR[TS][16];
    __shared__ float sY[TS][16];

    const int b  = blockIdx.y;
    const int d0 = blockIdx.x * 16;
    const int tid = threadIdx.x;
    const int n  = tid & 15;
    const int dl = tid >> 4;
    const int d  = d0 + dl;

    const float a = -__expf(A_log[d * NSc + n]);   // A[d][n]  (negative)
    float h = 0.0f;

    const size_t rowbase = (size_t)b * Lc;

    for (int l0 = 0; l0 < Lc; l0 += TS) {
        // cooperative stage: TS*16 = 2048 elements, 256 threads -> 8 each
        #pragma unroll
        for (int i = tid; i < TS * 16; i += 256) {
            int r = i >> 4, c = i & 15;
            size_t g = (rowbase + l0 + r) * DMc + d0 + c;
            sD[r][c] = delta_g[g];
            sX[r][c] = xs_g[g];
            sR[r][c] = res_g[g];
        }
        #pragma unroll
        for (int i = tid; i < TS * 16; i += 256) {
            size_t g = (rowbase + l0) * NSc + i;
            sB[i >> 4][i & 15] = bp_g[g];
            sC[i >> 4][i & 15] = cp_g[g];
        }
        __syncthreads();

        #pragma unroll 4
        for (int t = 0; t < TS; t++) {
            float dt = sD[t][dl];
            float xv = sX[t][dl];
            float dA = __expf(dt * a);
            h = fmaf(dA, h, dt * xv * sB[t][n]);
            float contrib = h * sC[t][n];
            // reduce over the 16 states (stays inside 16-lane halves)
            contrib += __shfl_xor_sync(0xffffffffu, contrib, 8);
            contrib += __shfl_xor_sync(0xffffffffu, contrib, 4);
            contrib += __shfl_xor_sync(0xffffffffu, contrib, 2);
            contrib += __shfl_xor_sync(0xffffffffu, contrib, 1);
            if (n == 0) sY[t][dl] = contrib;
        }
        __syncthreads();

        // epilogue: y = (scan + xs*D) * silu(res), coalesced store
        #pragma unroll
        for (int i = tid; i < TS * 16; i += 256) {
            int r = i >> 4, c = i & 15;
            size_t g = (rowbase + l0 + r) * DMc + d0 + c;
            float rv = sR[r][c];
            y_g[g] = (sY[r][c] + sX[r][c] * D_param[d0 + c]) * siluf(rv);
        }
        __syncthreads();
    }
}

// -------------------- launch ----------------------------------------------
extern "C" void kernel_launch(void* const* d_in, const int* in_sizes, int n_in,
                              void* d_out, int out_size)
{
    const float* x_in     = (const float*)d_in[0];
    const float* W_in     = (const float*)d_in[1];
    const float* W_res    = (const float*)d_in[2];
    const float* W_out    = (const float*)d_in[3];
    const float* conv_w   = (const float*)d_in[4];
    const float* conv_b   = (const float*)d_in[5];
    const float* A_log    = (const float*)d_in[6];
    const float* D_param  = (const float*)d_in[7];
    const float* W_B      = (const float*)d_in[8];
    const float* W_C      = (const float*)d_in[9];
    const float* W_dt     = (const float*)d_in[10];
    const float* W_dtproj = (const float*)d_in[11];
    const float* b_dtproj = (const float*)d_in[12];
    float* out = (float*)d_out;

    float *xpre, *res, *xs, *bp, *cp, *dtl, *delta, *y;
    cudaGetSymbolAddress((void**)&xpre,  g_xpre);
    cudaGetSymbolAddress((void**)&res,   g_res);
    cudaGetSymbolAddress((void**)&xs,    g_xs);
    cudaGetSymbolAddress((void**)&bp,    g_bp);
    cudaGetSymbolAddress((void**)&cp,    g_cp);
    cudaGetSymbolAddress((void**)&dtl,   g_dtl);
    cudaGetSymbolAddress((void**)&delta, g_delta);
    cudaGetSymbolAddress((void**)&y,     g_y);

    // 1+2) x_pre = x_in @ W_in^T ; res = x_in @ W_res^T  (fused, grid.z=2)
    gemm128<0><<<dim3(Mrows/GBM, DMc/GBN, 2), 256>>>(
        x_in, DINc, W_in, W_res, DINc, nullptr, xpre, res, DMc, DINc);
    // 3) xs = silu(causal_conv(x_pre) + b)   (float4 over d)
    conv_silu_kernel<<<(Mrows * DMc / 4) / 256, 256>>>(xpre, conv_w, conv_b, xs);
    // 4-6) fused skinny projections: Bp, Cp, dt_low in one pass over xs
    proj_bcdt<<<Mrows / PBM, 256>>>(xs, W_B, W_C, W_dt, bp, cp, dtl);
    // 7) delta = softplus(dt_low @ W_dtproj^T + b_dtproj)
    gemm128<1><<<dim3(Mrows/GBM, DMc/GBN, 1), 256>>>(
        dtl, RKc, W_dtproj, W_dtproj, RKc, b_dtproj, delta, delta, DMc, RKc);
    // 8) selective scan -> y (includes +xs*D and *silu(res))
    scan_kernel<<<dim3(DMc/16, Bc), 256>>>(delta, xs, bp, cp, res,
                                           A_log, D_param, y);
    // 9) out = y @ W_out^T  (4096 x 512, K=1024)
    gemm128<0><<<dim3(Mrows/GBM, DINc/GBN, 1), 256>>>(
        y, DMc, W_out, W_out, DMc, nullptr, out, out, DINc, DMc);
}